// round 17
// baseline (speedup 1.0000x reference)
#include <cuda_runtime.h>
#include <cuda_bf16.h>

#define N_NODES 50000
#define N_EDGES 800000
#define F0      128
#define H       64
#define NB      512
#define KTOP    30
#define CCH     32
#define LOUT    26      // KTOP - 5 + 1
#define FC1_IN  832     // 32*26
#define MAXN    1024
#define SCB     196     // scan blocks: 196*256 >= 50000

// ---------------- scratch (device globals; no allocation) ----------------
__device__ __align__(256) float g_C[N_NODES * 128];     // GEMM out: [ h@Wl | h@Wr ]
__device__ __align__(256) float g_h1[N_NODES * H];
__device__ __align__(256) float g_h2[N_NODES * H];
__device__ __align__(256) float g_wcat[3][F0 * 128];    // per-layer [Wl|Wr], K-major
__device__ __align__(256) float g_w1t[H * FC1_IN];      // lin1w transposed [64][832]
__device__ int   g_deg[N_NODES];
__device__ int   g_rowstart[N_NODES];
__device__ int   g_cursor[N_NODES];
__device__ int   g_csr[N_EDGES];
__device__ int   g_cnt[NB];
__device__ int   g_start[NB];
__device__ int   g_bsum[SCB];
__device__ int   g_boff[SCB];
__device__ __align__(256) float g_pool[NB * KTOP * H];
__device__ __align__(256) float g_conv[NB * FC1_IN];

// ---------------- init / counting ----------------
__global__ void zero_deg_cnt_k() {
    int i = blockIdx.x * blockDim.x + threadIdx.x;
    if (i < N_NODES) g_deg[i] = 0;
    if (i < NB) g_cnt[i] = 0;
}
__global__ void count_k(const int* __restrict__ dst, const int* __restrict__ batch) {
    int e = blockIdx.x * blockDim.x + threadIdx.x;
    if (e < N_EDGES) atomicAdd(&g_deg[dst[e]], 1);
    if (e < N_NODES) atomicAdd(&g_cnt[batch[e]], 1);
}

// ---------------- scans ----------------
__global__ void scanA_k() {            // per-block sums of g_deg
    __shared__ int s[256];
    int b = blockIdx.x, t = threadIdx.x;
    int idx = b * 256 + t;
    int v = (idx < N_NODES) ? g_deg[idx] : 0;
    s[t] = v;
    __syncthreads();
    for (int off = 1; off < 256; off <<= 1) {
        int u = (t >= off) ? s[t - off] : 0;
        __syncthreads();
        s[t] += u;
        __syncthreads();
    }
    if (t == 255) g_bsum[b] = s[255];
}
// block 0: scan SCB block sums -> g_boff ; block 1: graph starts from g_cnt
__global__ void scanB_k() {
    __shared__ int s[NB];
    int t = threadIdx.x;
    if (blockIdx.x == 0) {
        if (t < 256) {
            s[t] = (t < SCB) ? g_bsum[t] : 0;
        }
        __syncthreads();
        for (int off = 1; off < 256; off <<= 1) {
            int u = (t >= off && t < 256) ? s[t - off] : 0;
            __syncthreads();
            if (t < 256) s[t] += u;
            __syncthreads();
        }
        if (t < SCB) g_boff[t] = s[t] - g_bsum[t];
    } else {
        s[t] = g_cnt[t];
        __syncthreads();
        for (int off = 1; off < NB; off <<= 1) {
            int v = (t >= off) ? s[t - off] : 0;
            __syncthreads();
            s[t] += v;
            __syncthreads();
        }
        g_start[t] = s[t] - g_cnt[t];
    }
}
__global__ void scanC_k() {            // finalize rowstart / cursor
    __shared__ int s[256];
    int b = blockIdx.x, t = threadIdx.x;
    int idx = b * 256 + t;
    int v = (idx < N_NODES) ? g_deg[idx] : 0;
    s[t] = v;
    __syncthreads();
    for (int off = 1; off < 256; off <<= 1) {
        int u = (t >= off) ? s[t - off] : 0;
        __syncthreads();
        s[t] += u;
        __syncthreads();
    }
    if (idx < N_NODES) {
        int ex = g_boff[b] + s[t] - v;
        g_rowstart[idx] = ex;
        g_cursor[idx]   = ex;
    }
}
__global__ void fillcsr_k(const int* __restrict__ src, const int* __restrict__ dst) {
    int e = blockIdx.x * blockDim.x + threadIdx.x;
    if (e < N_EDGES) {
        int pos = atomicAdd(&g_cursor[dst[e]], 1);
        g_csr[pos] = src[e];
    }
}

// ---------------- weight prep ----------------
__global__ void wcat_all_k(const float* __restrict__ W1l, const float* __restrict__ W1r,
                           const float* __restrict__ W2l, const float* __restrict__ W2r,
                           const float* __restrict__ W3l, const float* __restrict__ W3r) {
    int i = blockIdx.x * blockDim.x + threadIdx.x;
    if (i < F0 * 64) {
        int k = i >> 6, j = i & 63;
        g_wcat[0][k * 128 + j]      = W1l[i];
        g_wcat[0][k * 128 + 64 + j] = W1r[i];
    } else if (i < F0 * 64 + H * 64) {
        int p = i - F0 * 64;
        int k = p >> 6, j = p & 63;
        g_wcat[1][k * 128 + j]      = W2l[p];
        g_wcat[1][k * 128 + 64 + j] = W2r[p];
    } else if (i < F0 * 64 + 2 * H * 64) {
        int p = i - F0 * 64 - H * 64;
        int k = p >> 6, j = p & 63;
        g_wcat[2][k * 128 + j]      = W3l[p];
        g_wcat[2][k * 128 + 64 + j] = W3r[p];
    }
}
__global__ void w1t_k(const float* __restrict__ w1) {
    int i = blockIdx.x * blockDim.x + threadIdx.x;  // 0..53247
    if (i < H * FC1_IN) {
        int r = i / FC1_IN, c = i % FC1_IN;
        g_w1t[i] = w1[c * H + r];
    }
}

// ---------------- GEMM v3: barrier-free mainloop, A from global regs, B smem-resident
// C[M x 128] = A[M x K] @ B[K x 128]; B staged in 64-row halves (32 KB).
template <int K>
__global__ __launch_bounds__(256, 2) void gemm_k(const float* __restrict__ A,
                                                 const float* __restrict__ B,
                                                 float* __restrict__ C) {
    __shared__ float sB[64][128];       // one 64-row half of B: 32 KB
    int t = threadIdx.x;
    int m0 = blockIdx.x * 128;
    int ty = t >> 4, tx = t & 15;       // 16x16 threads, 8 rows x 8 cols micro-tile
    int row0 = m0 + ty * 8;
    // clamp rows for loads (stores stay guarded); avoids OOB on last tile
    int rowA[8];
#pragma unroll
    for (int i = 0; i < 8; i++) {
        int r = row0 + i;
        rowA[i] = (r < N_NODES) ? r : (N_NODES - 1);
    }
    unsigned long long acc[8][4];       // packed pairs along j
#pragma unroll
    for (int i = 0; i < 8; i++)
#pragma unroll
        for (int q = 0; q < 4; q++) acc[i][q] = 0ULL;

#pragma unroll
    for (int h = 0; h < K / 64; h++) {
        // stage B half: 64 x 128 floats, 2048 float4, 8 per thread
#pragma unroll
        for (int i = 0; i < 8; i++) {
            int lin = t + i * 256;
            int brow = lin >> 5;
            int c4 = lin & 31;
            *(float4*)&sB[brow][c4 * 4] =
                *(const float4*)(B + (h * 64 + brow) * 128 + c4 * 4);
        }
        __syncthreads();

        for (int k0 = 0; k0 < 64; k0 += 4) {
            float4 a4[8];
#pragma unroll
            for (int i = 0; i < 8; i++)
                a4[i] = *(const float4*)(A + (long long)rowA[i] * K + h * 64 + k0);
#pragma unroll
            for (int kk = 0; kk < 4; kk++) {
                ulonglong2 bq0 = *(ulonglong2*)&sB[k0 + kk][tx * 8];
                ulonglong2 bq1 = *(ulonglong2*)&sB[k0 + kk][tx * 8 + 4];
#pragma unroll
                for (int i = 0; i < 8; i++) {
                    float av = (&a4[i].x)[kk];
                    unsigned int au = __float_as_uint(av);
                    unsigned long long ab;
                    asm("mov.b64 %0, {%1, %1};" : "=l"(ab) : "r"(au));
                    asm("fma.rn.f32x2 %0, %1, %2, %0;" : "+l"(acc[i][0]) : "l"(ab), "l"(bq0.x));
                    asm("fma.rn.f32x2 %0, %1, %2, %0;" : "+l"(acc[i][1]) : "l"(ab), "l"(bq0.y));
                    asm("fma.rn.f32x2 %0, %1, %2, %0;" : "+l"(acc[i][2]) : "l"(ab), "l"(bq1.x));
                    asm("fma.rn.f32x2 %0, %1, %2, %0;" : "+l"(acc[i][3]) : "l"(ab), "l"(bq1.y));
                }
            }
        }
        __syncthreads();
    }
#pragma unroll
    for (int i = 0; i < 8; i++) {
        int grow = row0 + i;
        if (grow < N_NODES) {
            ulonglong2 v0, v1;
            v0.x = acc[i][0]; v0.y = acc[i][1];
            v1.x = acc[i][2]; v1.y = acc[i][3];
            *(ulonglong2*)(C + (long long)grow * 128 + tx * 8)     = v0;
            *(ulonglong2*)(C + (long long)grow * 128 + tx * 8 + 4) = v1;
        }
    }
}

// ---------------- gather: out = relu( mean_{j in N(i)} C[j,:64] + C[i,64:] + b ) ----
__global__ void gather_k(const float4* __restrict__ C4, const float* __restrict__ bias,
                         float* __restrict__ out) {
    int node = blockIdx.x * 8 + (threadIdx.x >> 4);
    if (node >= N_NODES) return;
    int l = threadIdx.x & 15;
    int s = g_rowstart[node];
    int d = g_deg[node];
    float4 acc = make_float4(0.f, 0.f, 0.f, 0.f);
    int e = 0;
    for (; e + 4 <= d; e += 4) {
        int j0 = g_csr[s + e];
        int j1 = g_csr[s + e + 1];
        int j2 = g_csr[s + e + 2];
        int j3 = g_csr[s + e + 3];
        float4 a = C4[(long long)j0 * 32 + l];
        float4 b = C4[(long long)j1 * 32 + l];
        float4 c = C4[(long long)j2 * 32 + l];
        float4 dd = C4[(long long)j3 * 32 + l];
        acc.x += a.x + b.x + c.x + dd.x;
        acc.y += a.y + b.y + c.y + dd.y;
        acc.z += a.z + b.z + c.z + dd.z;
        acc.w += a.w + b.w + c.w + dd.w;
    }
    for (; e < d; e++) {
        float4 a = C4[(long long)g_csr[s + e] * 32 + l];
        acc.x += a.x; acc.y += a.y; acc.z += a.z; acc.w += a.w;
    }
    float dinv = 1.f / fmaxf((float)d, 1.f);
    float4 self = C4[(long long)node * 32 + 16 + l];
    float4 bv = ((const float4*)bias)[l];
    float4 r;
    r.x = fmaxf(acc.x * dinv + self.x + bv.x, 0.f);
    r.y = fmaxf(acc.y * dinv + self.y + bv.y, 0.f);
    r.z = fmaxf(acc.z * dinv + self.z + bv.z, 0.f);
    r.w = fmaxf(acc.w * dinv + self.w + bv.w, 0.f);
    ((float4*)out)[(long long)node * 16 + l] = r;
}

// ---------------- sort-pool: stable top-K by last channel desc (zero-pad fused) ----
__global__ void sortpool_k(const float* __restrict__ h) {
    int g = blockIdx.x;
    int tid = threadIdx.x;
    int s0 = g_start[g], n = g_cnt[g];
    __shared__ float v[MAXN];
    __shared__ int sel[KTOP];
    bool fits = (n <= MAXN);
    if (fits)
        for (int i = tid; i < n; i += blockDim.x)
            v[i] = h[(long long)(s0 + i) * H + (H - 1)];
    __syncthreads();
    for (int i = tid; i < n; i += blockDim.x) {
        float vi = fits ? v[i] : h[(long long)(s0 + i) * H + (H - 1)];
        int r = 0;
        for (int j = 0; j < n; j++) {
            float vj = fits ? v[j] : h[(long long)(s0 + j) * H + (H - 1)];
            r += (vj > vi) || (vj == vi && j < i);
            if (r >= KTOP) break;
        }
        if (r < KTOP) sel[r] = s0 + i;
    }
    __syncthreads();
    int m = n < KTOP ? n : KTOP;
    for (int idx = tid; idx < KTOP * H; idx += blockDim.x) {
        int r = idx >> 6, c = idx & 63;
        float val = (r < m) ? h[(long long)sel[r] * H + c] : 0.f;
        g_pool[((long long)g * KTOP + r) * H + c] = val;
    }
}

// ---------------- conv1d (NCH, OIH, VALID, kernel=5) + relu ----------------
__global__ void conv_k(const float* __restrict__ convw,
                       const float* __restrict__ convb) {
    int g = blockIdx.x;
    int tid = threadIdx.x;
    __shared__ float p[KTOP * H];
    __shared__ float sw[CCH * 321];
    for (int i = tid; i < KTOP * H; i += blockDim.x)
        p[i] = g_pool[(long long)g * KTOP * H + i];
    for (int i = tid; i < CCH * 320; i += blockDim.x) {
        int o = i / 320, c = i % 320;
        sw[o * 321 + c] = convw[i];
    }
    __syncthreads();
    for (int idx = tid; idx < CCH * LOUT; idx += blockDim.x) {
        int o = idx & 31;
        int t = idx >> 5;
        float acc = convb[o];
        const float* w = sw + o * 321;
#pragma unroll 4
        for (int i = 0; i < H; i++) {
#pragma unroll
            for (int hh = 0; hh < 5; hh++)
                acc = fmaf(p[(t + hh) * H + i], w[i * 5 + hh], acc);
        }
        g_conv[(long long)g * FC1_IN + o * LOUT + t] = fmaxf(acc, 0.f);
    }
}

// ---------------- FC1 + relu, FC2, log_softmax ----------------
__global__ void fc_k(const float* __restrict__ b1v,
                     const float* __restrict__ w2, const float* __restrict__ b2v,
                     float* __restrict__ out) {
    int g = blockIdx.x;
    int t = threadIdx.x;                   // 64 threads
    __shared__ float4 c4s[FC1_IN / 4];     // 208
    __shared__ float f[H];
    __shared__ float logits[10];
    const float4* cg = (const float4*)(g_conv + (long long)g * FC1_IN);
    for (int i = t; i < FC1_IN / 4; i += H) c4s[i] = cg[i];
    __syncthreads();
    float acc = b1v[t];
    const float4* wr = (const float4*)(g_w1t + (long long)t * FC1_IN);
#pragma unroll 4
    for (int k = 0; k < FC1_IN / 4; k++) {
        float4 cv = c4s[k];
        float4 wv = wr[k];
        acc = fmaf(cv.x, wv.x, acc);
        acc = fmaf(cv.y, wv.y, acc);
        acc = fmaf(cv.z, wv.z, acc);
        acc = fmaf(cv.w, wv.w, acc);
    }
    f[t] = fmaxf(acc, 0.f);
    __syncthreads();
    if (t < 10) {
        float a = b2v[t];
#pragma unroll
        for (int k = 0; k < H; k++) a = fmaf(f[k], w2[k * 10 + t], a);
        logits[t] = a;
    }
    __syncthreads();
    if (t == 0) {
        float mx = -1e30f;
        for (int i = 0; i < 10; i++) mx = fmaxf(mx, logits[i]);
        float s = 0.f;
        for (int i = 0; i < 10; i++) s += expf(logits[i] - mx);
        float ls = logf(s) + mx;
        for (int i = 0; i < 10; i++) out[g * 10 + i] = logits[i] - ls;
    }
}

extern "C" void kernel_launch(void* const* d_in, const int* in_sizes, int n_in,
                              void* d_out, int out_size) {
    const float* x     = (const float*)d_in[0];
    const int*   ei    = (const int*)d_in[1];      // int32 (JAX x64 disabled)
    const int*   batch = (const int*)d_in[2];      // int32
    const float* W1l = (const float*)d_in[3];
    const float* b1  = (const float*)d_in[4];
    const float* W1r = (const float*)d_in[5];
    const float* W2l = (const float*)d_in[6];
    const float* b2  = (const float*)d_in[7];
    const float* W2r = (const float*)d_in[8];
    const float* W3l = (const float*)d_in[9];
    const float* b3  = (const float*)d_in[10];
    const float* W3r = (const float*)d_in[11];
    const float* convw = (const float*)d_in[12];
    const float* convb = (const float*)d_in[13];
    const float* lin1w = (const float*)d_in[14];
    const float* lin1b = (const float*)d_in[15];
    const float* lin2w = (const float*)d_in[16];
    const float* lin2b = (const float*)d_in[17];
    const int* src = ei;
    const int* dst = ei + N_EDGES;
    float* out = (float*)d_out;

    float* wc0;  cudaGetSymbolAddress((void**)&wc0, g_wcat);
    float* wc1 = wc0 + F0 * 128;
    float* wc2 = wc0 + 2 * F0 * 128;
    float* Cbuf; cudaGetSymbolAddress((void**)&Cbuf, g_C);
    float* h1;   cudaGetSymbolAddress((void**)&h1, g_h1);
    float* h2;   cudaGetSymbolAddress((void**)&h2, g_h2);

    const int GB = (N_NODES + 127) / 128;
    const int AB = (N_NODES + 7) / 8;

    // index 0..2
    zero_deg_cnt_k<<<(N_NODES + 255) / 256, 256>>>();
    count_k<<<(N_EDGES + 255) / 256, 256>>>(dst, batch);
    wcat_all_k<<<(F0 * 64 + 2 * H * 64 + 255) / 256, 256>>>(W1l, W1r, W2l, W2r, W3l, W3r);

    // index 3: profiled slot — layer-1 GEMM (barrier-free mainloop)
    gemm_k<F0><<<GB, 256>>>(x, wc0, Cbuf);

    // CSR build + graph offsets + FC weight transpose
    scanA_k<<<SCB, 256>>>();
    scanB_k<<<2, NB>>>();              // block0: deg block-sum scan; block1: graph starts
    scanC_k<<<SCB, 256>>>();
    fillcsr_k<<<(N_EDGES + 255) / 256, 256>>>(src, dst);
    w1t_k<<<(H * FC1_IN + 255) / 256, 256>>>(lin1w);

    // layers
    gather_k<<<AB, 128>>>((const float4*)Cbuf, b1, h1);
    gemm_k<H><<<GB, 256>>>(h1, wc1, Cbuf);
    gather_k<<<AB, 128>>>((const float4*)Cbuf, b2, h2);
    gemm_k<H><<<GB, 256>>>(h2, wc2, Cbuf);
    gather_k<<<AB, 128>>>((const float4*)Cbuf, b3, h1);

    // sort-pool + conv + mlp + log_softmax
    sortpool_k<<<NB, 128>>>(h1);
    conv_k<<<NB, 256>>>(convw, convb);
    fc_k<<<NB, H>>>(lin1b, lin2w, lin2b, out);
}